// round 17
// baseline (speedup 1.0000x reference)
#include <cuda_runtime.h>
#include <cuda_bf16.h>
#include <cuda_fp16.h>
#include <math.h>

// ---------------------------------------------------------------------------
// GraphEncoder: 4-layer GATv2 on N=50000 nodes, E=800000 edges (+self loops).
//   - CSR over dst per launch (hist -> fused scan -> scatter).
//   - Layer 0: x0 = emb[node_type] has 3 distinct rows -> xl0/xr0 are 3x128
//     tables; edge pass gathers from shared memory (fp32).
//   - Layers 1-3: gemm2 (xl = x@Wl, xr = x@Wr) with packed fma.rn.f32x2.
//     xl is emitted as fp16 (half2) — it is ONLY used as the gather payload.
//   - Edge pass (R14 structure): persistent warps + global ticket, self-loop
//     hoisted, full 4-wide chunks + scalar tail, NO-MAX softmax with MUFU ex2,
//     fp16 gathers (half traffic), fused bias+residual+LayerNorm+ReLU.
// ---------------------------------------------------------------------------

#define NN 50000
#define EE 800000
#define SCAN_BLK 512

__device__ float    g_bufA[(size_t)NN * 128];
__device__ float    g_bufB[(size_t)NN * 128];
__device__ unsigned g_xlh[(size_t)NN * 64];   // fp16 xl: 64 half2 per node
__device__ float    g_xr[(size_t)NN * 128];
__device__ int      g_cnt[NN];
__device__ int      g_off[NN + 1];
__device__ int      g_cur[NN];
__device__ int      g_csr[EE];
__device__ int      g_bsum[SCAN_BLK];
__device__ float    g_wp[8 * 16384];  // packed weights, slots 2..7 (layers 1-3)
__device__ float    g_tl[384];        // layer-0 xl table [3][128] (fp32)
__device__ float    g_tr[384];        // layer-0 xr table [3][128]
__device__ int      g_tick[4];        // work tickets, one per edge launch

// ---------------------------------------------------------------------------
__device__ __forceinline__ unsigned long long ffma2(unsigned long long a,
                                                    unsigned long long b,
                                                    unsigned long long c) {
    unsigned long long d;
    asm("fma.rn.f32x2 %0, %1, %2, %3;" : "=l"(d) : "l"(a), "l"(b), "l"(c));
    return d;
}

__device__ __forceinline__ float pairsum(unsigned long long v) {
    float lo = __uint_as_float((unsigned)(v & 0xffffffffull));
    float hi = __uint_as_float((unsigned)(v >> 32));
    return lo + hi;
}

// guaranteed single-MUFU exp2
__device__ __forceinline__ float ex2(float x) {
    float y;
    asm("ex2.approx.ftz.f32 %0, %1;" : "=f"(y) : "f"(x));
    return y;
}

// ---------------------------------------------------------------------------
// prep: zero cnt, reset tickets, pack W (layers 1-3), build layer-0 tables.
__global__ void prep_kernel(const float* __restrict__ W1l, const float* __restrict__ W1r,
                            const float* __restrict__ W2l, const float* __restrict__ W2r,
                            const float* __restrict__ W3l, const float* __restrict__ W3r,
                            float* __restrict__ wp,
                            const float* __restrict__ emb,
                            const float* __restrict__ Wl0, const float* __restrict__ Wr0,
                            float* __restrict__ tl, float* __restrict__ tr,
                            int* __restrict__ tick, int* __restrict__ cnt, int n) {
    int gtid = blockIdx.x * blockDim.x + threadIdx.x;
    int gs = gridDim.x * blockDim.x;
    for (int i = gtid; i < n; i += gs) cnt[i] = 0;
    if (gtid < 4) tick[gtid] = 0;
    if (gtid < 3 * 16384) {
        int li = gtid / 16384, r = gtid - li * 16384;
        const float* Wl = (li == 0) ? W1l : (li == 1) ? W2l : W3l;
        const float* Wr = (li == 0) ? W1r : (li == 1) ? W2r : W3r;
        int k = r >> 7, c = r & 127;
        int o = (k >> 1) * 256 + c * 2 + (k & 1);
        float* dst = wp + (size_t)(2 * (li + 1)) * 16384;
        dst[o]         = Wl[r];
        dst[16384 + o] = Wr[r];
    } else if (gtid < 3 * 16384 + 384) {
        int t = gtid - 3 * 16384;
        int type = t >> 7, col = t & 127;
        float sl = 0.f, sr = 0.f;
#pragma unroll
        for (int k = 0; k < 16; k++) {
            float e = emb[type * 16 + k];
            sl = fmaf(e, Wl0[k * 128 + col], sl);
            sr = fmaf(e, Wr0[k * 128 + col], sr);
        }
        tl[t] = sl;
        tr[t] = sr;
    }
}

__global__ void hist_kernel(int* __restrict__ cnt, const int* __restrict__ dst, int E) {
    int e = blockIdx.x * blockDim.x + threadIdx.x;
    if (e < E) atomicAdd(&cnt[dst[e]], 1);
}

__global__ void block_sum_kernel(const int* __restrict__ cnt, int* __restrict__ bsum, int n) {
    __shared__ int sh[SCAN_BLK];
    int i = blockIdx.x * SCAN_BLK + threadIdx.x;
    sh[threadIdx.x] = (i < n) ? cnt[i] : 0;
    __syncthreads();
    for (int d = SCAN_BLK / 2; d > 0; d >>= 1) {
        if (threadIdx.x < d) sh[threadIdx.x] += sh[threadIdx.x + d];
        __syncthreads();
    }
    if (threadIdx.x == 0) bsum[blockIdx.x] = sh[0];
}

// fused: each block derives its own prefix (sum of bsum[0..bid)) then scans.
__global__ void block_scan_kernel(const int* __restrict__ cnt, const int* __restrict__ bsum,
                                  int* __restrict__ off, int* __restrict__ cur, int n) {
    __shared__ int sh[SCAN_BLK];
    int t = threadIdx.x;
    int pv = (t < blockIdx.x) ? bsum[t] : 0;
    sh[t] = pv;
    __syncthreads();
    for (int d = SCAN_BLK / 2; d > 0; d >>= 1) {
        if (t < d) sh[t] += sh[t + d];
        __syncthreads();
    }
    int bpre = sh[0];
    __syncthreads();
    int i = blockIdx.x * SCAN_BLK + t;
    int v = (i < n) ? cnt[i] : 0;
    sh[t] = v;
    __syncthreads();
    for (int d = 1; d < SCAN_BLK; d <<= 1) {
        int u = (t >= d) ? sh[t - d] : 0;
        __syncthreads();
        sh[t] += u;
        __syncthreads();
    }
    int excl = sh[t] - v + bpre;
    if (i < n) { off[i] = excl; cur[i] = excl; }
    if (i == n - 1) off[n] = excl + v;
}

__global__ void scatter_kernel(int* __restrict__ cur, const int* __restrict__ src,
                               const int* __restrict__ dst, int* __restrict__ csr, int E) {
    int e = blockIdx.x * blockDim.x + threadIdx.x;
    if (e < E) {
        int d = dst[e];
        int p = atomicAdd(&cur[d], 1);
        csr[p] = src[e];
    }
}

// ---------------------------------------------------------------------------
// gemm2: xl = x @ Wl (emitted fp16), xr = x @ Wr (fp32). K = 128.
__global__ void __launch_bounds__(128, 3)
gemm2_kernel(const float* __restrict__ x,
             const float* __restrict__ Wpl, const float* __restrict__ Wpr,
             unsigned* __restrict__ xlh, float* __restrict__ xr, int n) {
    const int K = 128;
    int w = (blockIdx.x * blockDim.x + threadIdx.x) >> 5;
    int lane = threadIdx.x & 31;
    int node0 = (w >> 1) * 8;
    if (node0 >= n) return;
    int col = ((w & 1) << 6) + lane * 2;

    unsigned long long aL[8][2], aR[8][2];
#pragma unroll
    for (int j = 0; j < 8; j++) {
        aL[j][0] = aL[j][1] = 0ull;
        aR[j][0] = aR[j][1] = 0ull;
    }

    const float* xp = x + (size_t)node0 * K;
    const float* wl = Wpl + col * 2;
    const float* wr = Wpr + col * 2;

    for (int k0 = 0; k0 < K; k0 += 4) {
        ulonglong2 xv[8];
#pragma unroll
        for (int j = 0; j < 8; j++)
            xv[j] = *(const ulonglong2*)(xp + (size_t)j * K + k0);
#pragma unroll
        for (int s = 0; s < 2; s++) {
            int k2 = (k0 >> 1) + s;
            ulonglong2 wlv = *(const ulonglong2*)(wl + k2 * 256);
            ulonglong2 wrv = *(const ulonglong2*)(wr + k2 * 256);
#pragma unroll
            for (int j = 0; j < 8; j++) {
                unsigned long long xb = s ? xv[j].y : xv[j].x;
                aL[j][0] = ffma2(wlv.x, xb, aL[j][0]);
                aL[j][1] = ffma2(wlv.y, xb, aL[j][1]);
                aR[j][0] = ffma2(wrv.x, xb, aR[j][0]);
                aR[j][1] = ffma2(wrv.y, xb, aR[j][1]);
            }
        }
    }
#pragma unroll
    for (int j = 0; j < 8; j++) {
        float2 rl = make_float2(pairsum(aL[j][0]), pairsum(aL[j][1]));
        float2 rr = make_float2(pairsum(aR[j][0]), pairsum(aR[j][1]));
        __half2 hl = __floats2half2_rn(rl.x, rl.y);
        xlh[(size_t)(node0 + j) * 64 + (col >> 1)] = *(unsigned*)&hl;
        *(float2*)(xr + (size_t)(node0 + j) * 128 + col) = rr;
    }
}

// ---------------------------------------------------------------------------
// Persistent edge pass (R14 structure). Self-loop hoisted; full 4-wide chunks
// + scalar tail. NO-MAX softmax with MUFU ex2 (att pre-scaled by log2 e).
// Gathers are fp16 (uint2 = 4 features) for non-NT layers.
template <int H, bool NT>
__global__ void gat_edge_kernel(const unsigned* __restrict__ xlh,
                                const float* __restrict__ tlf,  // NT table (fp32)
                                const float* __restrict__ xr,
                                const int* __restrict__ ntyp,
                                const float* __restrict__ xres,  // nullptr if no residual
                                const float* __restrict__ att, const float* __restrict__ bias,
                                const float* __restrict__ lng, const float* __restrict__ lnb,
                                const int* __restrict__ off, const int* __restrict__ csr,
                                float* __restrict__ out, int* __restrict__ tick, int n) {
    __shared__ float s_tl[NT ? 384 : 1];
    __shared__ float s_tr[NT ? 384 : 1];
    if (NT) {
        for (int i = threadIdx.x; i < 384; i += blockDim.x) {
            s_tl[i] = tlf[i];
            s_tr[i] = xr[i];   // NT: xr points at the 3x128 xr table
        }
        __syncthreads();
    }

    int lane = threadIdx.x & 31;
    int f_base;
    if (H == 4) f_base = ((lane >> 3) << 5) + ((lane & 7) << 2);
    else        f_base = lane << 2;
    constexpr int RED = (H == 4) ? 8 : 32;
    const float LOG2E = 1.4426950408889634f;

    float4 attv = *(const float4*)(att + f_base);
    attv.x *= LOG2E; attv.y *= LOG2E; attv.z *= LOG2E; attv.w *= LOG2E;
    float4 bv = *(const float4*)(bias + f_base);
    float4 gv = *(const float4*)(lng + f_base);
    float4 bb = *(const float4*)(lnb + f_base);

    auto loadrow = [&](int s) -> float4 {
        if (NT) {
            return *(const float4*)(s_tl + ntyp[s] * 128 + f_base);
        } else {
            uint2 u = *(const uint2*)(xlh + (size_t)s * 64 + (f_base >> 1));
            float2 lo = __half22float2(*(const __half2*)&u.x);
            float2 hi = __half22float2(*(const __half2*)&u.y);
            return make_float4(lo.x, lo.y, hi.x, hi.y);
        }
    };

    for (;;) {
        int base;
        if (lane == 0) base = atomicAdd(tick, 4);
        base = __shfl_sync(0xffffffffu, base, 0);
        if (base >= n) break;
        int nmax = min(base + 4, n);

        for (int node = base; node < nmax; node++) {
            float4 xrv;
            if (NT) xrv = *(const float4*)(s_tr + ntyp[node] * 128 + f_base);
            else    xrv = *(const float4*)(xr + (size_t)node * 128 + f_base);

            auto logit = [&](const float4& sv) -> float {
                float vx = fmaxf(sv.x + xrv.x, 0.2f * (sv.x + xrv.x));
                float vy = fmaxf(sv.y + xrv.y, 0.2f * (sv.y + xrv.y));
                float vz = fmaxf(sv.z + xrv.z, 0.2f * (sv.z + xrv.z));
                float vw = fmaxf(sv.w + xrv.w, 0.2f * (sv.w + xrv.w));
                return vx * attv.x + vy * attv.y + vz * attv.z + vw * attv.w;
            };

            int beg = off[node], end = off[node + 1];
            int deg = end - beg;
            int nfull = deg & ~3;

            // ---- self-loop (hoisted) ----
            float4 svs = loadrow(node);
            float ps = logit(svs);
#pragma unroll
            for (int o = 1; o < RED; o <<= 1)
                ps += __shfl_xor_sync(0xffffffffu, ps, o);
            float es = ex2(ps);
            float z = es;
            float4 acc;
            acc.x = es * svs.x; acc.y = es * svs.y;
            acc.z = es * svs.z; acc.w = es * svs.w;

            // ---- full 4-wide chunks over csr edges ----
            for (int i = 0; i < nfull; i += 4) {
                float4 sv0 = loadrow(csr[beg + i]);
                float4 sv1 = loadrow(csr[beg + i + 1]);
                float4 sv2 = loadrow(csr[beg + i + 2]);
                float4 sv3 = loadrow(csr[beg + i + 3]);

                float p0 = logit(sv0);
                float p1 = logit(sv1);
                float p2 = logit(sv2);
                float p3 = logit(sv3);
#pragma unroll
                for (int o = 1; o < RED; o <<= 1) {
                    p0 += __shfl_xor_sync(0xffffffffu, p0, o);
                    p1 += __shfl_xor_sync(0xffffffffu, p1, o);
                    p2 += __shfl_xor_sync(0xffffffffu, p2, o);
                    p3 += __shfl_xor_sync(0xffffffffu, p3, o);
                }
                float e0 = ex2(p0), e1 = ex2(p1), e2 = ex2(p2), e3 = ex2(p3);
                z += (e0 + e1) + (e2 + e3);
                acc.x = fmaf(e3, sv3.x, fmaf(e2, sv2.x, fmaf(e1, sv1.x, fmaf(e0, sv0.x, acc.x))));
                acc.y = fmaf(e3, sv3.y, fmaf(e2, sv2.y, fmaf(e1, sv1.y, fmaf(e0, sv0.y, acc.y))));
                acc.z = fmaf(e3, sv3.z, fmaf(e2, sv2.z, fmaf(e1, sv1.z, fmaf(e0, sv0.z, acc.z))));
                acc.w = fmaf(e3, sv3.w, fmaf(e2, sv2.w, fmaf(e1, sv1.w, fmaf(e0, sv0.w, acc.w))));
            }
            // ---- scalar tail (<= 3 items) ----
            for (int i = nfull; i < deg; i++) {
                float4 sv0 = loadrow(csr[beg + i]);
                float p0 = logit(sv0);
#pragma unroll
                for (int o = 1; o < RED; o <<= 1)
                    p0 += __shfl_xor_sync(0xffffffffu, p0, o);
                float e0 = ex2(p0);
                z += e0;
                acc.x = fmaf(e0, sv0.x, acc.x);
                acc.y = fmaf(e0, sv0.y, acc.y);
                acc.z = fmaf(e0, sv0.z, acc.z);
                acc.w = fmaf(e0, sv0.w, acc.w);
            }

            float invz = 1.f / z;
            float4 o4;
            o4.x = acc.x * invz + bv.x;
            o4.y = acc.y * invz + bv.y;
            o4.z = acc.z * invz + bv.z;
            o4.w = acc.w * invz + bv.w;
            if (xres) {
                float4 rv = *(const float4*)(xres + (size_t)node * 128 + f_base);
                o4.x += rv.x; o4.y += rv.y; o4.z += rv.z; o4.w += rv.w;
            }
            float s = o4.x + o4.y + o4.z + o4.w;
#pragma unroll
            for (int o = 1; o < 32; o <<= 1) s += __shfl_xor_sync(0xffffffffu, s, o);
            float mean = s * (1.0f / 128.0f);
            float dx = o4.x - mean, dy = o4.y - mean, dz = o4.z - mean, dw = o4.w - mean;
            float sq = dx * dx + dy * dy + dz * dz + dw * dw;
#pragma unroll
            for (int o = 1; o < 32; o <<= 1) sq += __shfl_xor_sync(0xffffffffu, sq, o);
            float r = rsqrtf(sq * (1.0f / 128.0f) + 1e-5f);
            o4.x = fmaxf(dx * r * gv.x + bb.x, 0.f);
            o4.y = fmaxf(dy * r * gv.y + bb.y, 0.f);
            o4.z = fmaxf(dz * r * gv.z + bb.z, 0.f);
            o4.w = fmaxf(dw * r * gv.w + bb.w, 0.f);
            *(float4*)(out + (size_t)node * 128 + f_base) = o4;
        }
    }
}

// ---------------------------------------------------------------------------
extern "C" void kernel_launch(void* const* d_in, const int* in_sizes, int n_in,
                              void* d_out, int out_size) {
    const int*   node_types = (const int*)d_in[0];
    const int*   ei         = (const int*)d_in[1];
    const float* emb        = (const float*)d_in[2];
    const float* lng        = (const float*)d_in[19];
    const float* lnb        = (const float*)d_in[20];

    int n = in_sizes[0];
    int E = in_sizes[1] / 2;
    const int* src = ei;
    const int* dst = ei + E;

    float *bufA, *bufB, *xr, *wp, *tl, *tr;
    unsigned *xlh;
    int *cnt, *off, *cur, *csr, *bsum, *tick;
    cudaGetSymbolAddress((void**)&bufA, g_bufA);
    cudaGetSymbolAddress((void**)&bufB, g_bufB);
    cudaGetSymbolAddress((void**)&xlh,  g_xlh);
    cudaGetSymbolAddress((void**)&xr,   g_xr);
    cudaGetSymbolAddress((void**)&cnt,  g_cnt);
    cudaGetSymbolAddress((void**)&off,  g_off);
    cudaGetSymbolAddress((void**)&cur,  g_cur);
    cudaGetSymbolAddress((void**)&csr,  g_csr);
    cudaGetSymbolAddress((void**)&bsum, g_bsum);
    cudaGetSymbolAddress((void**)&wp,   g_wp);
    cudaGetSymbolAddress((void**)&tl,   g_tl);
    cudaGetSymbolAddress((void**)&tr,   g_tr);
    cudaGetSymbolAddress((void**)&tick, g_tick);

    prep_kernel<<<(3 * 16384 + 384 + 255) / 256, 256>>>(
        (const float*)d_in[7], (const float*)d_in[8],
        (const float*)d_in[11], (const float*)d_in[12],
        (const float*)d_in[15], (const float*)d_in[16], wp,
        emb, (const float*)d_in[3], (const float*)d_in[4], tl, tr,
        tick, cnt, n);

    int nb = (n + SCAN_BLK - 1) / SCAN_BLK;
    hist_kernel<<<(E + 255) / 256, 256>>>(cnt, dst, E);
    block_sum_kernel<<<nb, SCAN_BLK>>>(cnt, bsum, n);
    block_scan_kernel<<<nb, SCAN_BLK>>>(cnt, bsum, off, cur, n);
    scatter_kernel<<<(E + 255) / 256, 256>>>(cur, src, dst, csr, E);

    int gemm_warps  = ((n + 7) / 8) * 2;
    int gemm_blocks = (gemm_warps + 3) / 4;
    int edge_blocks = 148 * 6;

    // ---- layer 0: fp32 tables in smem (xlh unused) ----
    gat_edge_kernel<4, true><<<edge_blocks, 256>>>(xlh, tl, tr, node_types, nullptr,
                                                   (const float*)d_in[5], (const float*)d_in[6],
                                                   lng + 0, lnb + 0, off, csr, bufB, tick + 0, n);
    // ---- layer 1: H=4, residual ----
    gemm2_kernel<<<gemm_blocks, 128>>>(bufB, wp + 2 * 16384, wp + 3 * 16384, xlh, xr, n);
    gat_edge_kernel<4, false><<<edge_blocks, 256>>>(xlh, nullptr, xr, nullptr, bufB,
                                                    (const float*)d_in[9], (const float*)d_in[10],
                                                    lng + 128, lnb + 128, off, csr, bufA, tick + 1, n);
    // ---- layer 2: H=4, residual ----
    gemm2_kernel<<<gemm_blocks, 128>>>(bufA, wp + 4 * 16384, wp + 5 * 16384, xlh, xr, n);
    gat_edge_kernel<4, false><<<edge_blocks, 256>>>(xlh, nullptr, xr, nullptr, bufA,
                                                    (const float*)d_in[13], (const float*)d_in[14],
                                                    lng + 256, lnb + 256, off, csr, bufB, tick + 2, n);
    // ---- layer 3: H=1, residual, writes final output ----
    gemm2_kernel<<<gemm_blocks, 128>>>(bufB, wp + 6 * 16384, wp + 7 * 16384, xlh, xr, n);
    gat_edge_kernel<1, false><<<edge_blocks, 256>>>(xlh, nullptr, xr, nullptr, bufB,
                                                    (const float*)d_in[17], (const float*)d_in[18],
                                                    lng + 384, lnb + 384, off, csr, (float*)d_out, tick + 3, n);
}